// round 5
// baseline (speedup 1.0000x reference)
#include <cuda_runtime.h>
#include <cuda_bf16.h>
#include <math.h>
#include <stdint.h>

// Problem constants
#define BB 32
#define LL 512
#define DD 1024
#define MM (BB * LL)   // 16384

// ---------------------------------------------------------------------------
// Global scratch (bf16 hi/lo pre-split copies; no allocations allowed)
// ---------------------------------------------------------------------------
__device__ __nv_bfloat16 g_Qh[(size_t)MM * DD], g_Ql[(size_t)MM * DD];
__device__ __nv_bfloat16 g_Ch[(size_t)MM * DD], g_Cl[(size_t)MM * DD];
__device__ __nv_bfloat16 g_Th[(size_t)MM * DD], g_Tl[(size_t)MM * DD];
__device__ __nv_bfloat16 g_Mh[(size_t)MM * DD], g_Ml[(size_t)MM * DD];
__device__ __nv_bfloat16 g_AH[(size_t)MM * LL], g_AL[(size_t)MM * LL];
__device__ __nv_bfloat16 g_W1h[(size_t)DD * DD], g_W1l[(size_t)DD * DD];
__device__ __nv_bfloat16 g_W2h[(size_t)DD * DD], g_W2l[(size_t)DD * DD];
__device__ __nv_bfloat16 g_Woh[(size_t)LL * DD], g_Wol[(size_t)LL * DD];
__device__ __nv_bfloat16 g_Wfh[(size_t)DD * 2 * DD], g_Wfl[(size_t)DD * 2 * DD];
__device__ float g_alpha_scratch[(size_t)MM * LL];

// ---------------------------------------------------------------------------
// Helpers
// ---------------------------------------------------------------------------
__device__ __forceinline__ uint32_t smem_u32(const void* p) {
    uint32_t a;
    asm("{ .reg .u64 t; cvta.to.shared.u64 t, %1; cvt.u32.u64 %0, t; }" : "=r"(a) : "l"(p));
    return a;
}
// pack: low16 = bf16(x), high16 = bf16(y)
__device__ __forceinline__ uint32_t pack_bf16x2(float x, float y) {
    uint32_t r;
    asm("cvt.rn.bf16x2.f32 %0, %1, %2;" : "=r"(r) : "f"(y), "f"(x));
    return r;
}
// split two floats into hi/lo bf16x2 words
__device__ __forceinline__ void split2(float x, float y, uint32_t& h, uint32_t& l) {
    h = pack_bf16x2(x, y);
    float hx = __uint_as_float(h << 16);
    float hy = __uint_as_float(h & 0xffff0000u);
    l = pack_bf16x2(x - hx, y - hy);
}
__device__ __forceinline__ void ldsm_x4(uint32_t& r0, uint32_t& r1, uint32_t& r2, uint32_t& r3,
                                        uint32_t addr) {
    asm volatile("ldmatrix.sync.aligned.m8n8.x4.shared.b16 {%0,%1,%2,%3}, [%4];"
                 : "=r"(r0), "=r"(r1), "=r"(r2), "=r"(r3) : "r"(addr));
}
__device__ __forceinline__ void ldsm_x4t(uint32_t& r0, uint32_t& r1, uint32_t& r2, uint32_t& r3,
                                         uint32_t addr) {
    asm volatile("ldmatrix.sync.aligned.m8n8.x4.trans.shared.b16 {%0,%1,%2,%3}, [%4];"
                 : "=r"(r0), "=r"(r1), "=r"(r2), "=r"(r3) : "r"(addr));
}
__device__ __forceinline__ void mma_bf16(float* d, const uint32_t* a, const uint32_t* b) {
    asm volatile(
        "mma.sync.aligned.m16n8k16.row.col.f32.bf16.bf16.f32 "
        "{%0,%1,%2,%3}, {%4,%5,%6,%7}, {%8,%9}, {%0,%1,%2,%3};"
        : "+f"(d[0]), "+f"(d[1]), "+f"(d[2]), "+f"(d[3])
        : "r"(a[0]), "r"(a[1]), "r"(a[2]), "r"(a[3]), "r"(b[0]), "r"(b[1]));
}
__device__ __forceinline__ void ldgsts16(uint32_t saddr, const void* g) {
    asm volatile("cp.async.ca.shared.global [%0], [%1], 16;" :: "r"(saddr), "l"(g));
}
#define CP_COMMIT() asm volatile("cp.async.commit_group;" ::: "memory")

// ---------------------------------------------------------------------------
// SMEM stage layout (bytes): Ah[128x64bf16]@0 (16K), Al@16K, Bh@32K, Bl@48K.
// NT B tile: [128 n][64 k]. BTRANS B tile: [64 k][128 n] (rows of 256B).
// Stage = 64KB, 3 stages = 192KB.
// ---------------------------------------------------------------------------
static constexpr int STAGE = 65536;
static constexpr int NSTAGE = 3;
static constexpr int SMEM_TOTAL = NSTAGE * STAGE;

// EPI: 0 = f32 plain, 1 = tanh(acc + b0 + b1) -> bf16 hi/lo,
//      2 = acc + b0 -> f32, 3 = plain -> bf16 hi/lo
template <bool DUAL, bool BTRANS, int EPI>
__global__ __launch_bounds__(256, 1)
void tc_gemm(const __nv_bfloat16* __restrict__ Ah0, const __nv_bfloat16* __restrict__ Al0,
             const __nv_bfloat16* __restrict__ Ah1, const __nv_bfloat16* __restrict__ Al1,
             const __nv_bfloat16* __restrict__ Bh0, const __nv_bfloat16* __restrict__ Bl0,
             const __nv_bfloat16* __restrict__ Bh1, const __nv_bfloat16* __restrict__ Bl1,
             const float* __restrict__ bias0, const float* __restrict__ bias1,
             float* __restrict__ Cf, __nv_bfloat16* __restrict__ Oh, __nv_bfloat16* __restrict__ Ol,
             int K, int lda, int ldb, int ldc,
             long sA, long sB, long sC)
{
    extern __shared__ char smem[];
    const uint32_t sb = smem_u32(smem);
    const int tid = threadIdx.x;
    const int wid = tid >> 5;
    const int lane = tid & 31;
    const int wm = wid >> 2;          // 0..1 : 64 rows
    const int wn = wid & 3;           // 0..3 : 32 cols
    const int rowBase = blockIdx.y * 128;
    const int colBase = blockIdx.x * 128;
    const long z = blockIdx.z;

    const int kc = K / 64;
    const int C_CH = DUAL ? 2 * kc : kc;

    float acc[4][4][4];
#pragma unroll
    for (int i = 0; i < 4; i++)
#pragma unroll
        for (int j = 0; j < 4; j++)
#pragma unroll
            for (int r = 0; r < 4; r++) acc[i][j][r] = 0.f;

    auto loadChunk = [&](int c, int s) {
        const bool first = (!DUAL || c < kc);
        const __nv_bfloat16* ah = first ? Ah0 : Ah1;
        const __nv_bfloat16* al = first ? Al0 : Al1;
        const __nv_bfloat16* bh = first ? Bh0 : Bh1;
        const __nv_bfloat16* bl = first ? Bl0 : Bl1;
        const int k0 = (first ? c : c - kc) * 64;
        const uint32_t st = sb + s * STAGE;
        // A tiles: 128 rows x 8 chunks(16B)
        {
            const int lc = tid & 7;
            const int r0 = tid >> 3;   // 0..31
#pragma unroll
            for (int it = 0; it < 4; it++) {
                const int row = r0 + it * 32;
                const uint32_t so = row * 128 + ((lc ^ (row & 7)) << 4);
                const size_t go = z * sA + (size_t)(rowBase + row) * lda + k0 + lc * 8;
                ldgsts16(st + so, ah + go);
                ldgsts16(st + 16384 + so, al + go);
            }
        }
        if (!BTRANS) {
            const int lc = tid & 7;
            const int r0 = tid >> 3;
#pragma unroll
            for (int it = 0; it < 4; it++) {
                const int row = r0 + it * 32;
                const uint32_t so = row * 128 + ((lc ^ (row & 7)) << 4);
                const size_t go = z * sB + (size_t)(colBase + row) * ldb + k0 + lc * 8;
                ldgsts16(st + 32768 + so, bh + go);
                ldgsts16(st + 49152 + so, bl + go);
            }
        } else {
            const int lc = tid & 15;
            const int r0 = tid >> 4;   // 0..15
#pragma unroll
            for (int it = 0; it < 4; it++) {
                const int row = r0 + it * 16;   // k-row 0..63
                const uint32_t so = row * 256 + ((lc ^ ((row & 7) << 1)) << 4);
                const size_t go = z * sB + (size_t)(k0 + row) * ldb + colBase + lc * 8;
                ldgsts16(st + 32768 + so, bh + go);
                ldgsts16(st + 49152 + so, bl + go);
            }
        }
    };

    auto computeChunk = [&](int s) {
        const uint32_t st = sb + s * STAGE;
#pragma unroll
        for (int ks = 0; ks < 4; ks++) {
            uint32_t ah[4][4], al[4][4], bh[4][2], bl[4][2];
#pragma unroll
            for (int mt = 0; mt < 4; mt++) {
                const int row = wm * 64 + mt * 16 + (lane & 15);
                const int lc = ks * 2 + (lane >> 4);
                const uint32_t off = row * 128 + ((lc ^ (row & 7)) << 4);
                ldsm_x4(ah[mt][0], ah[mt][1], ah[mt][2], ah[mt][3], st + off);
                ldsm_x4(al[mt][0], al[mt][1], al[mt][2], al[mt][3], st + 16384 + off);
            }
#pragma unroll
            for (int p = 0; p < 2; p++) {
                uint32_t q0, q1, q2, q3;
                if (BTRANS) {
                    const int k = ks * 16 + (lane & 15);
                    const int lc = wn * 4 + p * 2 + (lane >> 4);
                    const uint32_t off = k * 256 + ((lc ^ ((k & 7) << 1)) << 4);
                    ldsm_x4t(q0, q1, q2, q3, st + 32768 + off);
                    bh[2 * p][0] = q0; bh[2 * p][1] = q1;
                    bh[2 * p + 1][0] = q2; bh[2 * p + 1][1] = q3;
                    ldsm_x4t(q0, q1, q2, q3, st + 49152 + off);
                    bl[2 * p][0] = q0; bl[2 * p][1] = q1;
                    bl[2 * p + 1][0] = q2; bl[2 * p + 1][1] = q3;
                } else {
                    const int row = wn * 32 + p * 16 + (lane & 15);
                    const int lc = ks * 2 + (lane >> 4);
                    const uint32_t off = row * 128 + ((lc ^ (row & 7)) << 4);
                    ldsm_x4(q0, q1, q2, q3, st + 32768 + off);
                    bh[2 * p][0] = q0; bh[2 * p][1] = q2;
                    bh[2 * p + 1][0] = q1; bh[2 * p + 1][1] = q3;
                    ldsm_x4(q0, q1, q2, q3, st + 49152 + off);
                    bl[2 * p][0] = q0; bl[2 * p][1] = q2;
                    bl[2 * p + 1][0] = q1; bl[2 * p + 1][1] = q3;
                }
            }
#pragma unroll
            for (int mt = 0; mt < 4; mt++)
#pragma unroll
                for (int nt = 0; nt < 4; nt++) {
                    mma_bf16(acc[mt][nt], ah[mt], bh[nt]);   // hi*hi
                    mma_bf16(acc[mt][nt], ah[mt], bl[nt]);   // hi*lo
                    mma_bf16(acc[mt][nt], al[mt], bh[nt]);   // lo*hi
                }
        }
    };

    // Multistage pipeline: stages 0,1 prefetched; issue c+2 before compute(c).
    loadChunk(0, 0); CP_COMMIT();
    loadChunk(1, 1); CP_COMMIT();
    for (int c = 0; c < C_CH; ++c) {
        if (c + 2 < C_CH) {
            asm volatile("cp.async.wait_group 1;" ::: "memory");
            __syncthreads();
            loadChunk(c + 2, (c + 2) % NSTAGE);
            CP_COMMIT();
        } else {
            asm volatile("cp.async.wait_group 0;" ::: "memory");
            __syncthreads();
        }
        computeChunk(c % NSTAGE);
        __syncthreads();
    }

    // Epilogue
    const int lr = lane >> 2, lcn = (lane & 3) * 2;
#pragma unroll
    for (int mt = 0; mt < 4; mt++) {
        const int r0 = rowBase + wm * 64 + mt * 16 + lr;
#pragma unroll
        for (int nt = 0; nt < 4; nt++) {
            const int c0 = colBase + wn * 32 + nt * 8 + lcn;
            float v0 = acc[mt][nt][0], v1 = acc[mt][nt][1];
            float v2 = acc[mt][nt][2], v3 = acc[mt][nt][3];
            if (EPI == 1) {
                const float s0 = bias0[c0] + bias1[c0];
                const float s1 = bias0[c0 + 1] + bias1[c0 + 1];
                v0 = tanhf(v0 + s0); v1 = tanhf(v1 + s1);
                v2 = tanhf(v2 + s0); v3 = tanhf(v3 + s1);
            }
            if (EPI == 2) {
                v0 += bias0[c0]; v1 += bias0[c0 + 1];
                v2 += bias0[c0]; v3 += bias0[c0 + 1];
            }
            if (EPI == 0 || EPI == 2) {
                float* p0 = Cf + z * sC + (size_t)r0 * ldc + c0;
                *reinterpret_cast<float2*>(p0) = make_float2(v0, v1);
                *reinterpret_cast<float2*>(p0 + 8 * ldc) = make_float2(v2, v3);
            } else {
                uint32_t h, l;
                const size_t o0 = z * sC + (size_t)r0 * ldc + c0;
                const size_t o1 = o0 + 8 * (size_t)ldc;
                split2(v0, v1, h, l);
                *reinterpret_cast<uint32_t*>(Oh + o0) = h;
                *reinterpret_cast<uint32_t*>(Ol + o0) = l;
                split2(v2, v3, h, l);
                *reinterpret_cast<uint32_t*>(Oh + o1) = h;
                *reinterpret_cast<uint32_t*>(Ol + o1) = l;
            }
        }
    }
}

// ---------------------------------------------------------------------------
// Elementwise f32 -> bf16 hi/lo split
// ---------------------------------------------------------------------------
__global__ __launch_bounds__(256)
void split_kernel(const float4* __restrict__ in, uint2* __restrict__ hi,
                  uint2* __restrict__ lo, int n4)
{
    int i = blockIdx.x * 256 + threadIdx.x;
    if (i >= n4) return;
    float4 v = in[i];
    uint32_t h0, l0, h1, l1;
    split2(v.x, v.y, h0, l0);
    split2(v.z, v.w, h1, l1);
    hi[i] = make_uint2(h0, h1);
    lo[i] = make_uint2(l0, l1);
}

// ---------------------------------------------------------------------------
// In-place row softmax over 512 elems + bf16 hi/lo emission.
// ---------------------------------------------------------------------------
__global__ __launch_bounds__(128)
void softmax512(float* __restrict__ X, __nv_bfloat16* __restrict__ Ah,
                __nv_bfloat16* __restrict__ Al)
{
    const int row = blockIdx.x;
    const int t = threadIdx.x;
    const int lane = t & 31, wd = t >> 5;
    __shared__ float red[4];

    float4 v = *reinterpret_cast<float4*>(&X[(size_t)row * LL + t * 4]);

    float m = fmaxf(fmaxf(v.x, v.y), fmaxf(v.z, v.w));
#pragma unroll
    for (int off = 16; off > 0; off >>= 1)
        m = fmaxf(m, __shfl_xor_sync(0xffffffffu, m, off));
    if (lane == 0) red[wd] = m;
    __syncthreads();
    const float rm = fmaxf(fmaxf(red[0], red[1]), fmaxf(red[2], red[3]));
    __syncthreads();

    v.x = __expf(v.x - rm); v.y = __expf(v.y - rm);
    v.z = __expf(v.z - rm); v.w = __expf(v.w - rm);

    float s = v.x + v.y + v.z + v.w;
#pragma unroll
    for (int off = 16; off > 0; off >>= 1)
        s += __shfl_xor_sync(0xffffffffu, s, off);
    if (lane == 0) red[wd] = s;
    __syncthreads();
    const float inv = 1.0f / (red[0] + red[1] + red[2] + red[3]);

    v.x *= inv; v.y *= inv; v.z *= inv; v.w *= inv;
    *reinterpret_cast<float4*>(&X[(size_t)row * LL + t * 4]) = v;

    uint32_t h0, l0, h1, l1;
    split2(v.x, v.y, h0, l0);
    split2(v.z, v.w, h1, l1);
    *reinterpret_cast<uint2*>(Ah + (size_t)row * LL + t * 4) = make_uint2(h0, h1);
    *reinterpret_cast<uint2*>(Al + (size_t)row * LL + t * 4) = make_uint2(l0, l1);
}

// ---------------------------------------------------------------------------
// Launcher
// ---------------------------------------------------------------------------
extern "C" void kernel_launch(void* const* d_in, const int* in_sizes, int n_in,
                              void* d_out, int out_size)
{
    const float* query   = (const float*)d_in[0];
    const float* context = (const float*)d_in[1];
    const float* W_in    = (const float*)d_in[2];
    const float* b_in    = (const float*)d_in[3];
    const float* W_in2   = (const float*)d_in[4];
    const float* b_in2   = (const float*)d_in[5];
    const float* W_out   = (const float*)d_in[6];
    const float* W_fc    = (const float*)d_in[7];
    const float* b_fc    = (const float*)d_in[8];

    float* out = (float*)d_out;

    __nv_bfloat16 *Qh, *Ql, *Ch, *Cl, *Th, *Tl, *Mh, *Ml, *AH, *AL;
    __nv_bfloat16 *W1h, *W1l, *W2h, *W2l, *Woh, *Wol, *Wfh, *Wfl;
    float* alphaFallback;
    cudaGetSymbolAddress((void**)&Qh, g_Qh);   cudaGetSymbolAddress((void**)&Ql, g_Ql);
    cudaGetSymbolAddress((void**)&Ch, g_Ch);   cudaGetSymbolAddress((void**)&Cl, g_Cl);
    cudaGetSymbolAddress((void**)&Th, g_Th);   cudaGetSymbolAddress((void**)&Tl, g_Tl);
    cudaGetSymbolAddress((void**)&Mh, g_Mh);   cudaGetSymbolAddress((void**)&Ml, g_Ml);
    cudaGetSymbolAddress((void**)&AH, g_AH);   cudaGetSymbolAddress((void**)&AL, g_AL);
    cudaGetSymbolAddress((void**)&W1h, g_W1h); cudaGetSymbolAddress((void**)&W1l, g_W1l);
    cudaGetSymbolAddress((void**)&W2h, g_W2h); cudaGetSymbolAddress((void**)&W2l, g_W2l);
    cudaGetSymbolAddress((void**)&Woh, g_Woh); cudaGetSymbolAddress((void**)&Wol, g_Wol);
    cudaGetSymbolAddress((void**)&Wfh, g_Wfh); cudaGetSymbolAddress((void**)&Wfl, g_Wfl);
    cudaGetSymbolAddress((void**)&alphaFallback, g_alpha_scratch);

    float* alpha = ((size_t)out_size >= (size_t)MM * (DD + LL))
                       ? out + (size_t)MM * DD
                       : alphaFallback;

    cudaFuncSetAttribute(tc_gemm<true,  false, 1>, cudaFuncAttributeMaxDynamicSharedMemorySize, SMEM_TOTAL);
    cudaFuncSetAttribute(tc_gemm<false, false, 0>, cudaFuncAttributeMaxDynamicSharedMemorySize, SMEM_TOTAL);
    cudaFuncSetAttribute(tc_gemm<false, true,  3>, cudaFuncAttributeMaxDynamicSharedMemorySize, SMEM_TOTAL);
    cudaFuncSetAttribute(tc_gemm<true,  false, 2>, cudaFuncAttributeMaxDynamicSharedMemorySize, SMEM_TOTAL);

    // 0) Pre-split inputs/weights to bf16 hi/lo
    auto splitLaunch = [&](const float* src, __nv_bfloat16* h, __nv_bfloat16* l, size_t n) {
        int n4 = (int)(n / 4);
        split_kernel<<<(n4 + 255) / 256, 256>>>((const float4*)src, (uint2*)h, (uint2*)l, n4);
    };
    splitLaunch(query,   Qh,  Ql,  (size_t)MM * DD);
    splitLaunch(context, Ch,  Cl,  (size_t)MM * DD);
    splitLaunch(W_in,    W1h, W1l, (size_t)DD * DD);
    splitLaunch(W_in2,   W2h, W2l, (size_t)DD * DD);
    splitLaunch(W_out,   Woh, Wol, (size_t)LL * DD);
    splitLaunch(W_fc,    Wfh, Wfl, (size_t)DD * 2 * DD);

    // 1) T = tanh(q@W_in^T + c@W_in2^T + b_in + b_in2) -> bf16 hi/lo
    tc_gemm<true, false, 1><<<dim3(DD / 128, MM / 128, 1), 256, SMEM_TOTAL>>>(
        Qh, Ql, Ch, Cl, W1h, W1l, W2h, W2l, b_in, b_in2,
        nullptr, Th, Tl, DD, DD, DD, DD, 0, 0, 0);

    // 2) logits = T @ W_out^T -> f32 alpha
    tc_gemm<false, false, 0><<<dim3(LL / 128, MM / 128, 1), 256, SMEM_TOTAL>>>(
        Th, Tl, nullptr, nullptr, Woh, Wol, nullptr, nullptr, nullptr, nullptr,
        alpha, nullptr, nullptr, DD, DD, DD, LL, 0, 0, 0);

    // 3) softmax (f32 in-place) + bf16 hi/lo emission
    softmax512<<<MM, 128>>>(alpha, AH, AL);

    // 4) mix[b] = alpha[b] @ context[b] -> bf16 hi/lo (NN, batched)
    tc_gemm<false, true, 3><<<dim3(DD / 128, LL / 128, BB), 256, SMEM_TOTAL>>>(
        AH, AL, nullptr, nullptr, Ch, Cl, nullptr, nullptr, nullptr, nullptr,
        nullptr, Mh, Ml, LL, LL, DD, DD,
        (long)LL * LL, (long)LL * DD, (long)LL * DD);

    // 5) out = mix@Wfc[:,:D]^T + context@Wfc[:,D:]^T + b_fc -> f32
    tc_gemm<true, false, 2><<<dim3(DD / 128, MM / 128, 1), 256, SMEM_TOTAL>>>(
        Mh, Ml, Ch, Cl, Wfh, Wfl, Wfh + DD, Wfl + DD, b_fc, nullptr,
        out, nullptr, nullptr, DD, DD, 2 * DD, DD, 0, 0, 0);
}